// round 4
// baseline (speedup 1.0000x reference)
#include <cuda_runtime.h>
#include <cstdint>

typedef unsigned long long ull;

static constexpr int NN = 49152;        // nodes
static constexpr int NE = 786432;       // edges
static constexpr int T  = 8192;         // LSTM sequence length (B)
static constexpr int NB = 6;            // ACT (LSTM batch)
static constexpr int CC = 128;          // channels
static constexpr int HH = 32;           // hidden
static constexpr int PF = 4;            // pre prefetch depth (steps)

// ---------------- scratch (static device globals; no allocs) ----------------
__device__ int   g_deg[NN];             // in-degree (no self loop)
__device__ float g_dinv[NN];
__device__ int   g_rowptr[NN + 1];
__device__ int   g_cursor[NN];
__device__ int   g_csrc[NE];
__device__ float g_xw[NN * CC];                    // state @ conv_w^T
__device__ float g_x [NN * CC];                    // relu(gcn)+state
// permuted LSTM input projection: [m][j][{i,f,g,o}], m = t*NB+b  (+PF pad)
__device__ float g_pre[(NN + PF * NB) * CC];
__device__ float g_hs[T * NB * HH];                // LSTM hidden states

// ---------------- f32x2 helpers (FFMA2 path, sm_100+) ----------------
__device__ __forceinline__ ull pk2(float lo, float hi) {
    ull r; asm("mov.b64 %0, {%1,%2};" : "=l"(r) : "f"(lo), "f"(hi)); return r;
}
__device__ __forceinline__ void upk2(ull v, float& lo, float& hi) {
    asm("mov.b64 {%0,%1}, %2;" : "=f"(lo), "=f"(hi) : "l"(v));
}
__device__ __forceinline__ ull fma2(ull a, ull b, ull c) {
    ull d; asm("fma.rn.f32x2 %0, %1, %2, %3;" : "=l"(d) : "l"(a), "l"(b), "l"(c)); return d;
}
__device__ __forceinline__ ull add2(ull a, ull b) {
    ull d; asm("add.rn.f32x2 %0, %1, %2;" : "=l"(d) : "l"(a), "l"(b)); return d;
}

// minimal-chain MUFU nonlinearities (exact-ish: ex2+rcp, ~2 ulp)
__device__ __forceinline__ float ex2f(float x) {
    float y; asm("ex2.approx.f32 %0, %1;" : "=f"(y) : "f"(x)); return y;
}
__device__ __forceinline__ float rcpf(float x) {
    float y; asm("rcp.approx.f32 %0, %1;" : "=f"(y) : "f"(x)); return y;
}
__device__ __forceinline__ float sigm_f(float x) {
    return rcpf(1.0f + ex2f(-1.4426950408889634f * x));
}
__device__ __forceinline__ float tanh_g(float x) {
    return fmaf(-2.0f, rcpf(ex2f(2.8853900817779268f * x) + 1.0f), 1.0f);
}

// ---------------- K0: zero degree ----------------
__global__ void k_init_deg() {
    int i = blockIdx.x * blockDim.x + threadIdx.x;
    if (i < NN) g_deg[i] = 0;
}

// ---------------- K1: count in-degree at dst ----------------
__global__ void k_count(const int* __restrict__ ei) {
    int e = blockIdx.x * blockDim.x + threadIdx.x;
    if (e < NE) atomicAdd(&g_deg[ei[NE + e]], 1);
}

// ---------------- K2: fused scan (rowptr/cursor) + dinv, 1 block ------------
__global__ __launch_bounds__(1024) void k_scan() {
    __shared__ int warp_base[32];
    const int tid  = threadIdx.x;
    const int lane = tid & 31;
    const int wid  = tid >> 5;
    const int base = tid * 48;

    int s = 0;
    #pragma unroll 8
    for (int i = 0; i < 48; i++) s += g_deg[base + i];

    int incl = s;
    #pragma unroll
    for (int o = 1; o < 32; o <<= 1) {
        int n = __shfl_up_sync(0xffffffffu, incl, o);
        if (lane >= o) incl += n;
    }
    if (lane == 31) warp_base[wid] = incl;
    __syncthreads();
    if (wid == 0) {
        int t = warp_base[lane];
        int wi = t;
        #pragma unroll
        for (int o = 1; o < 32; o <<= 1) {
            int n = __shfl_up_sync(0xffffffffu, wi, o);
            if (lane >= o) wi += n;
        }
        warp_base[lane] = wi - t;
    }
    __syncthreads();

    int run = warp_base[wid] + (incl - s);
    #pragma unroll 8
    for (int i = 0; i < 48; i++) {
        int d = g_deg[base + i];
        g_rowptr[base + i] = run;
        g_cursor[base + i] = run;
        g_dinv  [base + i] = rsqrtf((float)(d + 1));
        run += d;
    }
    if (tid == 1023) g_rowptr[NN] = run;
}

// ---------------- K4: fill CSR (src lists by dst) ----------------
__global__ void k_fill(const int* __restrict__ ei) {
    int e = blockIdx.x * blockDim.x + threadIdx.x;
    if (e < NE) {
        int s = ei[e];
        int d = ei[NE + e];
        int pos = atomicAdd(&g_cursor[d], 1);
        g_csrc[pos] = s;
    }
}

// ---------------- K5: xw = state @ conv_w^T  (M=NN, N=128, K=128) ----------
__global__ __launch_bounds__(256, 2) void k_gemm_conv(const float* __restrict__ A,
                                                      const float* __restrict__ W) {
    __shared__ float As[16][132];
    __shared__ float Bs[16][132];
    const int tid  = threadIdx.x;
    const int bm   = blockIdx.x * 128;
    const int tRow = tid >> 4, tCol = tid & 15;
    float acc[8][8];
    #pragma unroll
    for (int i = 0; i < 8; i++)
        #pragma unroll
        for (int j = 0; j < 8; j++) acc[i][j] = 0.0f;

    for (int k0 = 0; k0 < 128; k0 += 16) {
        #pragma unroll
        for (int i = 0; i < 2; i++) {
            int aid = tid * 2 + i;
            int row = aid >> 2, c4 = aid & 3;
            float4 v = *(const float4*)(A + (size_t)(bm + row) * 128 + k0 + c4 * 4);
            As[c4 * 4 + 0][row] = v.x; As[c4 * 4 + 1][row] = v.y;
            As[c4 * 4 + 2][row] = v.z; As[c4 * 4 + 3][row] = v.w;
        }
        #pragma unroll
        for (int i = 0; i < 2; i++) {
            int wid = tid * 2 + i;
            int n = wid >> 2, c4 = wid & 3;
            float4 v = *(const float4*)(W + (size_t)n * 128 + k0 + c4 * 4);
            Bs[c4 * 4 + 0][n] = v.x; Bs[c4 * 4 + 1][n] = v.y;
            Bs[c4 * 4 + 2][n] = v.z; Bs[c4 * 4 + 3][n] = v.w;
        }
        __syncthreads();
        #pragma unroll
        for (int k = 0; k < 16; k++) {
            float4 a0 = *(const float4*)&As[k][tRow * 8];
            float4 a1 = *(const float4*)&As[k][tRow * 8 + 4];
            float4 b0 = *(const float4*)&Bs[k][tCol * 8];
            float4 b1 = *(const float4*)&Bs[k][tCol * 8 + 4];
            float av[8] = {a0.x, a0.y, a0.z, a0.w, a1.x, a1.y, a1.z, a1.w};
            float bv[8] = {b0.x, b0.y, b0.z, b0.w, b1.x, b1.y, b1.z, b1.w};
            #pragma unroll
            for (int i = 0; i < 8; i++)
                #pragma unroll
                for (int j = 0; j < 8; j++) acc[i][j] = fmaf(av[i], bv[j], acc[i][j]);
        }
        __syncthreads();
    }
    #pragma unroll
    for (int i = 0; i < 8; i++) {
        float4 o0 = {acc[i][0], acc[i][1], acc[i][2], acc[i][3]};
        float4 o1 = {acc[i][4], acc[i][5], acc[i][6], acc[i][7]};
        size_t base = (size_t)(bm + tRow * 8 + i) * 128 + tCol * 8;
        *(float4*)(g_xw + base)     = o0;
        *(float4*)(g_xw + base + 4) = o1;
    }
}

// ---------------- K6: gather-aggregate + bias + relu + residual -> g_x ------
__global__ __launch_bounds__(256) void k_gather(const float* __restrict__ state,
                                                const float* __restrict__ conv_b) {
    const int lane = threadIdx.x & 31;
    const int v = blockIdx.x * 8 + (threadIdx.x >> 5);
    const float dv = g_dinv[v];
    const float4* xwv = (const float4*)(g_xw + (size_t)v * CC);
    float4 a = xwv[lane];
    float4 acc;
    acc.x = a.x * dv; acc.y = a.y * dv; acc.z = a.z * dv; acc.w = a.w * dv;

    const int s0 = g_rowptr[v], s1 = g_rowptr[v + 1];
    for (int base = s0; base < s1; base += 32) {
        int m = s1 - base; if (m > 32) m = 32;
        int   s_l = 0; float d_l = 0.0f;
        if (lane < m) { s_l = g_csrc[base + lane]; d_l = g_dinv[s_l]; }
        #pragma unroll 4
        for (int i = 0; i < m; i++) {
            int   s = __shfl_sync(0xffffffffu, s_l, i);
            float w = __shfl_sync(0xffffffffu, d_l, i);
            float4 xv = ((const float4*)(g_xw + (size_t)s * CC))[lane];
            acc.x = fmaf(xv.x, w, acc.x);
            acc.y = fmaf(xv.y, w, acc.y);
            acc.z = fmaf(xv.z, w, acc.z);
            acc.w = fmaf(xv.w, w, acc.w);
        }
    }
    float4 cb = ((const float4*)conv_b)[lane];
    float4 st = ((const float4*)(state + (size_t)v * CC))[lane];
    float4 r;
    r.x = fmaxf(acc.x * dv + cb.x, 0.0f) + st.x;
    r.y = fmaxf(acc.y * dv + cb.y, 0.0f) + st.y;
    r.z = fmaxf(acc.z * dv + cb.z, 0.0f) + st.z;
    r.w = fmaxf(acc.w * dv + cb.w, 0.0f) + st.w;
    ((float4*)(g_x + (size_t)v * CC))[lane] = r;
}

// -------- K7: pre = x @ w_ih[:,:128]^T + action*w_ih[:,128] + bias ----------
// output PERMUTED: g_pre[(m*32 + j)*4 + gamma], n = gamma*32 + j
__global__ __launch_bounds__(256, 2) void k_gemm_pre(const float* __restrict__ Wih,
                                                     const float* __restrict__ action,
                                                     const float* __restrict__ bih,
                                                     const float* __restrict__ bhh) {
    __shared__ float As[16][132];
    __shared__ float Bs[16][132];
    const int tid  = threadIdx.x;
    const int bm   = blockIdx.x * 128;
    const int tRow = tid >> 4, tCol = tid & 15;
    const float* A = g_x;
    float acc[8][8];
    #pragma unroll
    for (int i = 0; i < 8; i++)
        #pragma unroll
        for (int j = 0; j < 8; j++) acc[i][j] = 0.0f;

    for (int k0 = 0; k0 < 128; k0 += 16) {
        #pragma unroll
        for (int i = 0; i < 2; i++) {
            int aid = tid * 2 + i;
            int row = aid >> 2, c4 = aid & 3;
            float4 v = *(const float4*)(A + (size_t)(bm + row) * 128 + k0 + c4 * 4);
            As[c4 * 4 + 0][row] = v.x; As[c4 * 4 + 1][row] = v.y;
            As[c4 * 4 + 2][row] = v.z; As[c4 * 4 + 3][row] = v.w;
        }
        #pragma unroll
        for (int i = 0; i < 8; i++) {
            int idx = tid + i * 256;
            int n = idx >> 4, k = idx & 15;
            Bs[k][n] = Wih[(size_t)n * 129 + k0 + k];
        }
        __syncthreads();
        #pragma unroll
        for (int k = 0; k < 16; k++) {
            float4 a0 = *(const float4*)&As[k][tRow * 8];
            float4 a1 = *(const float4*)&As[k][tRow * 8 + 4];
            float4 b0 = *(const float4*)&Bs[k][tCol * 8];
            float4 b1 = *(const float4*)&Bs[k][tCol * 8 + 4];
            float av[8] = {a0.x, a0.y, a0.z, a0.w, a1.x, a1.y, a1.z, a1.w};
            float bv[8] = {b0.x, b0.y, b0.z, b0.w, b1.x, b1.y, b1.z, b1.w};
            #pragma unroll
            for (int i = 0; i < 8; i++)
                #pragma unroll
                for (int j = 0; j < 8; j++) acc[i][j] = fmaf(av[i], bv[j], acc[i][j]);
        }
        __syncthreads();
    }
    const int n0 = tCol * 8;
    const int gamma = n0 >> 5;         // constant over the 8 consecutive n
    const int jbase = n0 & 31;
    float wc[8], bi[8];
    #pragma unroll
    for (int jj = 0; jj < 8; jj++) {
        wc[jj] = Wih[(size_t)(n0 + jj) * 129 + 128];
        bi[jj] = bih[n0 + jj] + bhh[n0 + jj];
    }
    #pragma unroll
    for (int i = 0; i < 8; i++) {
        int m = bm + tRow * 8 + i;
        float am = action[m];
        #pragma unroll
        for (int jj = 0; jj < 8; jj++) {
            float val = acc[i][jj] + am * wc[jj] + bi[jj];
            g_pre[((size_t)m * 32 + jbase + jj) * 4 + gamma] = val;
        }
    }
}

// ---------------- K8: LSTM — one warp drives TWO batch lanes ----------------
// Two independent recurrences interleaved in one warp hide each other's
// latency. lane j owns h_j,c_j of both lanes; all 4 gates per j.
// h exchanged through warp-private smem (STS + syncwarp + 8x LDS.128).
__global__ __launch_bounds__(32, 1) void k_lstm(const float* __restrict__ w_hh) {
    const int b0 = blockIdx.x * 2;
    const int j  = threadIdx.x;
    __shared__ __align__(16) float sh_h[2][32];

    // shared weights: 4 gates x 16 packed f32x2 (128 regs)
    ull w2[4][16];
    #pragma unroll
    for (int g = 0; g < 4; g++) {
        const float* wr = w_hh + (size_t)(g * 32 + j) * 32;
        #pragma unroll
        for (int q = 0; q < 16; q++) w2[g][q] = pk2(wr[2 * q], wr[2 * q + 1]);
    }

    float c[2] = {0.0f, 0.0f};
    sh_h[0][j] = 0.0f; sh_h[1][j] = 0.0f;

    const float4* pre4 = (const float4*)g_pre;   // [m*32 + j]
    float4 preq[2][PF];
    #pragma unroll
    for (int v = 0; v < 2; v++)
        #pragma unroll
        for (int i = 0; i < PF; i++)
            preq[v][i] = pre4[((size_t)i * NB + b0 + v) * 32 + j];

    const ulonglong2* hp0 = (const ulonglong2*)&sh_h[0][0];  // packed h pairs
    const ulonglong2* hp1 = (const ulonglong2*)&sh_h[1][0];
    float* hs0 = g_hs + (size_t)(b0 + 0) * HH + j;
    float* hs1 = g_hs + (size_t)(b0 + 1) * HH + j;
    __syncwarp();

    for (int t = 0; t < T; t += PF) {
        #pragma unroll
        for (int u = 0; u < PF; u++) {
            const int tt = t + u;
            const float4 p0 = preq[0][u];
            const float4 p1 = preq[1][u];
            preq[0][u] = pre4[((size_t)(tt + PF) * NB + b0 + 0) * 32 + j];
            preq[1][u] = pre4[((size_t)(tt + PF) * NB + b0 + 1) * 32 + j];

            // read both h vectors as packed pairs (broadcast LDS, no conflicts)
            ull h0[16], h1[16];
            #pragma unroll
            for (int q = 0; q < 8; q++) {
                ulonglong2 v0 = hp0[q];
                ulonglong2 v1 = hp1[q];
                h0[2 * q] = v0.x; h0[2 * q + 1] = v0.y;
                h1[2 * q] = v1.x; h1[2 * q + 1] = v1.y;
            }

            // matvec: per batch, 4 gates x 2 chains of depth 8; bias seeded
            ull A0[2][4], A1[2][4];
            const float pb0[4] = {p0.x, p0.y, p0.z, p0.w};
            const float pb1[4] = {p1.x, p1.y, p1.z, p1.w};
            #pragma unroll
            for (int g = 0; g < 4; g++) {
                A0[0][g] = fma2(h0[0], w2[g][0], pk2(pb0[g], 0.0f));
                A0[1][g] = fma2(h1[0], w2[g][0], pk2(pb1[g], 0.0f));
                A1[0][g] = fma2(h0[1], w2[g][1], pk2(0.0f, 0.0f));
                A1[1][g] = fma2(h1[1], w2[g][1], pk2(0.0f, 0.0f));
            }
            #pragma unroll
            for (int q = 2; q < 16; q += 2) {
                #pragma unroll
                for (int g = 0; g < 4; g++) {
                    A0[0][g] = fma2(h0[q],     w2[g][q],     A0[0][g]);
                    A0[1][g] = fma2(h1[q],     w2[g][q],     A0[1][g]);
                    A1[0][g] = fma2(h0[q + 1], w2[g][q + 1], A1[0][g]);
                    A1[1][g] = fma2(h1[q + 1], w2[g][q + 1], A1[1][g]);
                }
            }

            float hn[2];
            #pragma unroll
            for (int v = 0; v < 2; v++) {
                float a[4];
                #pragma unroll
                for (int g = 0; g < 4; g++) {
                    ull s = add2(A0[v][g], A1[v][g]);
                    float lo, hi; upk2(s, lo, hi);
                    a[g] = lo + hi;
                }
                const float gi = sigm_f(a[0]);
                const float gf = sigm_f(a[1]);
                const float gg = tanh_g(a[2]);
                const float go = sigm_f(a[3]);
                c[v] = fmaf(gf, c[v], gi * gg);
                const float no2 = -2.0f * go;
                const float E = ex2f(2.8853900817779268f * c[v]);
                const float r = rcpf(E + 1.0f);
                hn[v] = fmaf(no2, r, go);          // o * tanh(c)
            }

            sh_h[0][j] = hn[0];
            sh_h[1][j] = hn[1];
            hs0[(size_t)tt * (NB * HH)] = hn[0];
            hs1[(size_t)tt * (NB * HH)] = hn[1];
            __syncwarp();
        }
    }
}

// ---------------- K9: head  out[t] = lin2_b + sum_b lin2 . relu(lin1 h + b1)
__global__ __launch_bounds__(256) void k_head(const float* __restrict__ lin1,
                                              const float* __restrict__ b1,
                                              const float* __restrict__ lin2,
                                              const float* __restrict__ l2b,
                                              float* __restrict__ out) {
    __shared__ float s1[32][33];
    __shared__ float sb1[32], s2[32];
    const int tid = threadIdx.x;
    if (tid < 32) { sb1[tid] = b1[tid]; s2[tid] = lin2[tid]; }
    for (int i = tid; i < 1024; i += 256) s1[i >> 5][i & 31] = lin1[i];
    __syncthreads();

    const int warp = tid >> 5, lane = tid & 31;
    float l1r[32];
    #pragma unroll
    for (int k = 0; k < 32; k++) l1r[k] = s1[lane][k];
    const float l2l = s2[lane], b1l = sb1[lane];
    const float l2bias = l2b[0];

    const int t0 = (blockIdx.x * 8 + warp) * 8;
    for (int q = 0; q < 8; q++) {
        const int t = t0 + q;
        const float* hp = g_hs + (size_t)t * (NB * HH);
        float partial = 0.0f;
        #pragma unroll
        for (int bb = 0; bb < NB; bb++) {
            float hv = hp[bb * 32 + lane];
            float acc = b1l;
            #pragma unroll
            for (int k = 0; k < 32; k++)
                acc = fmaf(l1r[k], __shfl_sync(0xffffffffu, hv, k), acc);
            partial = fmaf(l2l, fmaxf(acc, 0.0f), partial);
        }
        #pragma unroll
        for (int o = 16; o; o >>= 1) partial += __shfl_xor_sync(0xffffffffu, partial, o);
        if (lane == 0) out[t] = partial + l2bias;
    }
}

// ---------------- launch ----------------
extern "C" void kernel_launch(void* const* d_in, const int* in_sizes, int n_in,
                              void* d_out, int out_size) {
    const float* state  = (const float*)d_in[0];
    const int*   ei     = (const int*)  d_in[1];
    const float* action = (const float*)d_in[2];
    const float* conv_w = (const float*)d_in[3];
    const float* conv_b = (const float*)d_in[4];
    const float* w_ih   = (const float*)d_in[5];
    const float* w_hh   = (const float*)d_in[6];
    const float* b_ih   = (const float*)d_in[7];
    const float* b_hh   = (const float*)d_in[8];
    const float* lin1_w = (const float*)d_in[9];
    const float* lin1_b = (const float*)d_in[10];
    const float* lin2_w = (const float*)d_in[11];
    const float* lin2_b = (const float*)d_in[12];
    float* out = (float*)d_out;

    k_init_deg<<<NN / 256, 256>>>();
    k_count   <<<NE / 256, 256>>>(ei);
    k_scan    <<<1, 1024>>>();
    k_fill    <<<NE / 256, 256>>>(ei);
    k_gemm_conv<<<NN / 128, 256>>>(state, conv_w);
    k_gather  <<<NN / 8, 256>>>(state, conv_b);
    k_gemm_pre<<<NN / 128, 256>>>(w_ih, action, b_ih, b_hh);
    k_lstm    <<<NB / 2, 32>>>(w_hh);
    k_head    <<<T / 64, 256>>>(lin1_w, lin1_b, lin2_w, lin2_b, out);
}

// round 5
// speedup vs baseline: 1.5416x; 1.5416x over previous
#include <cuda_runtime.h>
#include <cstdint>

typedef unsigned long long ull;

static constexpr int NN = 49152;        // nodes
static constexpr int NE = 786432;       // edges
static constexpr int T  = 8192;         // LSTM sequence length (B)
static constexpr int NB = 6;            // ACT (LSTM batch)
static constexpr int CC = 128;          // channels
static constexpr int HH = 32;           // hidden
static constexpr int PF = 4;            // pre prefetch depth (steps)

// ---------------- scratch (static device globals; no allocs) ----------------
__device__ int   g_deg[NN];             // in-degree (no self loop)
__device__ float g_dinv[NN];
__device__ int   g_rowptr[NN + 1];
__device__ int   g_cursor[NN];
__device__ int   g_csrc[NE];
__device__ float g_xw[NN * CC];                    // state @ conv_w^T
__device__ float g_x [NN * CC];                    // relu(gcn)+state
__device__ float g_pre[(NN + PF * NB) * CC];       // LSTM input projection (+pad)
__device__ float g_hs[T * NB * HH];                // LSTM hidden states

// ---------------- f32x2 helpers (FFMA2 path, sm_100+) ----------------
__device__ __forceinline__ ull pk2(float lo, float hi) {
    ull r; asm("mov.b64 %0, {%1,%2};" : "=l"(r) : "f"(lo), "f"(hi)); return r;
}
__device__ __forceinline__ void upk2(ull v, float& lo, float& hi) {
    asm("mov.b64 {%0,%1}, %2;" : "=f"(lo), "=f"(hi) : "l"(v));
}
__device__ __forceinline__ ull fma2(ull a, ull b, ull c) {
    ull d; asm("fma.rn.f32x2 %0, %1, %2, %3;" : "=l"(d) : "l"(a), "l"(b), "l"(c)); return d;
}
__device__ __forceinline__ ull mul2(ull a, ull b) {
    ull d; asm("mul.rn.f32x2 %0, %1, %2;" : "=l"(d) : "l"(a), "l"(b)); return d;
}
__device__ __forceinline__ ull add2(ull a, ull b) {
    ull d; asm("add.rn.f32x2 %0, %1, %2;" : "=l"(d) : "l"(a), "l"(b)); return d;
}

// R1's activation forms (measured-good)
__device__ __forceinline__ float sigm_f(float x) {
    float e = __expf(-x);
    return __fdividef(1.0f, 1.0f + e);
}
__device__ __forceinline__ float tanh_f(float x) {
    float e = __expf(2.0f * x);           // inf/0 handled: -> +/-1
    return 1.0f - __fdividef(2.0f, e + 1.0f);
}

// ---------------- K0: zero degree ----------------
__global__ void k_init_deg() {
    int i = blockIdx.x * blockDim.x + threadIdx.x;
    if (i < NN) g_deg[i] = 0;
}

// ---------------- K1: count in-degree at dst ----------------
__global__ void k_count(const int* __restrict__ ei) {
    int e = blockIdx.x * blockDim.x + threadIdx.x;
    if (e < NE) atomicAdd(&g_deg[ei[NE + e]], 1);
}

// ---------------- K2: fused scan (rowptr/cursor) + dinv, 1 block ------------
__global__ __launch_bounds__(1024) void k_scan() {
    __shared__ int warp_base[32];
    const int tid  = threadIdx.x;
    const int lane = tid & 31;
    const int wid  = tid >> 5;
    const int base = tid * 48;

    int s = 0;
    #pragma unroll 8
    for (int i = 0; i < 48; i++) s += g_deg[base + i];

    int incl = s;
    #pragma unroll
    for (int o = 1; o < 32; o <<= 1) {
        int n = __shfl_up_sync(0xffffffffu, incl, o);
        if (lane >= o) incl += n;
    }
    if (lane == 31) warp_base[wid] = incl;
    __syncthreads();
    if (wid == 0) {
        int t = warp_base[lane];
        int wi = t;
        #pragma unroll
        for (int o = 1; o < 32; o <<= 1) {
            int n = __shfl_up_sync(0xffffffffu, wi, o);
            if (lane >= o) wi += n;
        }
        warp_base[lane] = wi - t;
    }
    __syncthreads();

    int run = warp_base[wid] + (incl - s);
    #pragma unroll 8
    for (int i = 0; i < 48; i++) {
        int d = g_deg[base + i];
        g_rowptr[base + i] = run;
        g_cursor[base + i] = run;
        g_dinv  [base + i] = rsqrtf((float)(d + 1));
        run += d;
    }
    if (tid == 1023) g_rowptr[NN] = run;
}

// ---------------- K4: fill CSR (src lists by dst) ----------------
__global__ void k_fill(const int* __restrict__ ei) {
    int e = blockIdx.x * blockDim.x + threadIdx.x;
    if (e < NE) {
        int s = ei[e];
        int d = ei[NE + e];
        int pos = atomicAdd(&g_cursor[d], 1);
        g_csrc[pos] = s;
    }
}

// ---------------- K5: xw = state @ conv_w^T  (M=NN, N=128, K=128) ----------
__global__ __launch_bounds__(256, 2) void k_gemm_conv(const float* __restrict__ A,
                                                      const float* __restrict__ W) {
    __shared__ float As[16][132];
    __shared__ float Bs[16][132];
    const int tid  = threadIdx.x;
    const int bm   = blockIdx.x * 128;
    const int tRow = tid >> 4, tCol = tid & 15;
    float acc[8][8];
    #pragma unroll
    for (int i = 0; i < 8; i++)
        #pragma unroll
        for (int j = 0; j < 8; j++) acc[i][j] = 0.0f;

    for (int k0 = 0; k0 < 128; k0 += 16) {
        #pragma unroll
        for (int i = 0; i < 2; i++) {
            int aid = tid * 2 + i;            // 0..511
            int row = aid >> 2, c4 = aid & 3;
            float4 v = *(const float4*)(A + (size_t)(bm + row) * 128 + k0 + c4 * 4);
            As[c4 * 4 + 0][row] = v.x; As[c4 * 4 + 1][row] = v.y;
            As[c4 * 4 + 2][row] = v.z; As[c4 * 4 + 3][row] = v.w;
        }
        #pragma unroll
        for (int i = 0; i < 2; i++) {
            int wid = tid * 2 + i;
            int n = wid >> 2, c4 = wid & 3;
            float4 v = *(const float4*)(W + (size_t)n * 128 + k0 + c4 * 4);
            Bs[c4 * 4 + 0][n] = v.x; Bs[c4 * 4 + 1][n] = v.y;
            Bs[c4 * 4 + 2][n] = v.z; Bs[c4 * 4 + 3][n] = v.w;
        }
        __syncthreads();
        #pragma unroll
        for (int k = 0; k < 16; k++) {
            float4 a0 = *(const float4*)&As[k][tRow * 8];
            float4 a1 = *(const float4*)&As[k][tRow * 8 + 4];
            float4 b0 = *(const float4*)&Bs[k][tCol * 8];
            float4 b1 = *(const float4*)&Bs[k][tCol * 8 + 4];
            float av[8] = {a0.x, a0.y, a0.z, a0.w, a1.x, a1.y, a1.z, a1.w};
            float bv[8] = {b0.x, b0.y, b0.z, b0.w, b1.x, b1.y, b1.z, b1.w};
            #pragma unroll
            for (int i = 0; i < 8; i++)
                #pragma unroll
                for (int j = 0; j < 8; j++) acc[i][j] = fmaf(av[i], bv[j], acc[i][j]);
        }
        __syncthreads();
    }
    #pragma unroll
    for (int i = 0; i < 8; i++) {
        float4 o0 = {acc[i][0], acc[i][1], acc[i][2], acc[i][3]};
        float4 o1 = {acc[i][4], acc[i][5], acc[i][6], acc[i][7]};
        size_t base = (size_t)(bm + tRow * 8 + i) * 128 + tCol * 8;
        *(float4*)(g_xw + base)     = o0;
        *(float4*)(g_xw + base + 4) = o1;
    }
}

// ---------------- K6: gather-aggregate + bias + relu + residual -> g_x ------
__global__ __launch_bounds__(256) void k_gather(const float* __restrict__ state,
                                                const float* __restrict__ conv_b) {
    const int lane = threadIdx.x & 31;
    const int v = blockIdx.x * 8 + (threadIdx.x >> 5);
    const float dv = g_dinv[v];
    const float4* xwv = (const float4*)(g_xw + (size_t)v * CC);
    float4 a = xwv[lane];
    float4 acc;                      // self loop contribution (norm = dv*dv)
    acc.x = a.x * dv; acc.y = a.y * dv; acc.z = a.z * dv; acc.w = a.w * dv;

    const int s0 = g_rowptr[v], s1 = g_rowptr[v + 1];
    for (int base = s0; base < s1; base += 32) {
        int m = s1 - base; if (m > 32) m = 32;
        int   s_l = 0; float d_l = 0.0f;
        if (lane < m) { s_l = g_csrc[base + lane]; d_l = g_dinv[s_l]; }
        #pragma unroll 4
        for (int i = 0; i < m; i++) {
            int   s = __shfl_sync(0xffffffffu, s_l, i);
            float w = __shfl_sync(0xffffffffu, d_l, i);
            float4 xv = ((const float4*)(g_xw + (size_t)s * CC))[lane];
            acc.x = fmaf(xv.x, w, acc.x);
            acc.y = fmaf(xv.y, w, acc.y);
            acc.z = fmaf(xv.z, w, acc.z);
            acc.w = fmaf(xv.w, w, acc.w);
        }
    }
    float4 cb = ((const float4*)conv_b)[lane];
    float4 st = ((const float4*)(state + (size_t)v * CC))[lane];
    float4 r;
    r.x = fmaxf(acc.x * dv + cb.x, 0.0f) + st.x;
    r.y = fmaxf(acc.y * dv + cb.y, 0.0f) + st.y;
    r.z = fmaxf(acc.z * dv + cb.z, 0.0f) + st.z;
    r.w = fmaxf(acc.w * dv + cb.w, 0.0f) + st.w;
    ((float4*)(g_x + (size_t)v * CC))[lane] = r;
}

// ---------------- K7: pre = x @ w_ih[:, :128]^T + action*w_ih[:,128] + bias -
__global__ __launch_bounds__(256, 2) void k_gemm_pre(const float* __restrict__ Wih,
                                                     const float* __restrict__ action,
                                                     const float* __restrict__ bih,
                                                     const float* __restrict__ bhh) {
    __shared__ float As[16][132];
    __shared__ float Bs[16][132];
    const int tid  = threadIdx.x;
    const int bm   = blockIdx.x * 128;
    const int tRow = tid >> 4, tCol = tid & 15;
    const float* A = g_x;
    float acc[8][8];
    #pragma unroll
    for (int i = 0; i < 8; i++)
        #pragma unroll
        for (int j = 0; j < 8; j++) acc[i][j] = 0.0f;

    for (int k0 = 0; k0 < 128; k0 += 16) {
        #pragma unroll
        for (int i = 0; i < 2; i++) {
            int aid = tid * 2 + i;
            int row = aid >> 2, c4 = aid & 3;
            float4 v = *(const float4*)(A + (size_t)(bm + row) * 128 + k0 + c4 * 4);
            As[c4 * 4 + 0][row] = v.x; As[c4 * 4 + 1][row] = v.y;
            As[c4 * 4 + 2][row] = v.z; As[c4 * 4 + 3][row] = v.w;
        }
        // w_ih rows have stride 129 -> scalar loads
        #pragma unroll
        for (int i = 0; i < 8; i++) {
            int idx = tid + i * 256;          // 0..2047
            int n = idx >> 4, k = idx & 15;
            Bs[k][n] = Wih[(size_t)n * 129 + k0 + k];
        }
        __syncthreads();
        #pragma unroll
        for (int k = 0; k < 16; k++) {
            float4 a0 = *(const float4*)&As[k][tRow * 8];
            float4 a1 = *(const float4*)&As[k][tRow * 8 + 4];
            float4 b0 = *(const float4*)&Bs[k][tCol * 8];
            float4 b1 = *(const float4*)&Bs[k][tCol * 8 + 4];
            float av[8] = {a0.x, a0.y, a0.z, a0.w, a1.x, a1.y, a1.z, a1.w};
            float bv[8] = {b0.x, b0.y, b0.z, b0.w, b1.x, b1.y, b1.z, b1.w};
            #pragma unroll
            for (int i = 0; i < 8; i++)
                #pragma unroll
                for (int j = 0; j < 8; j++) acc[i][j] = fmaf(av[i], bv[j], acc[i][j]);
        }
        __syncthreads();
    }
    const int n0 = tCol * 8;
    float wc[8], bi[8];
    #pragma unroll
    for (int j = 0; j < 8; j++) {
        wc[j] = Wih[(size_t)(n0 + j) * 129 + 128];
        bi[j] = bih[n0 + j] + bhh[n0 + j];
    }
    #pragma unroll
    for (int i = 0; i < 8; i++) {
        int m = bm + tRow * 8 + i;
        float am = action[m];
        float o[8];
        #pragma unroll
        for (int j = 0; j < 8; j++) o[j] = acc[i][j] + am * wc[j] + bi[j];
        float4 o0 = {o[0], o[1], o[2], o[3]};
        float4 o1 = {o[4], o[5], o[6], o[7]};
        size_t base = (size_t)m * 128 + n0;
        *(float4*)(g_pre + base)     = o0;
        *(float4*)(g_pre + base + 4) = o1;
    }
}

// ---------------- K8: LSTM recurrence (R1 structure, shfl h-exchange) -------
// block b handles batch lane b; warp gamma computes gate gamma (i,f,g,o rows).
// h lives in registers (lane j of every warp holds h_j redundantly); the
// packed-pair view needed by the matvec is rebuilt with 32 independent SHFLs,
// removing R1's STS h + __syncwarp + LDS h serial segment.
__global__ __launch_bounds__(128, 1) void k_lstm(const float* __restrict__ w_hh) {
    const int b     = blockIdx.x;
    const int tid   = threadIdx.x;             // == row r of W_hh (0..127)
    const int gamma = tid >> 5;
    const int j     = tid & 31;
    __shared__ __align__(16) float sh_g[2][128];    // [parity][j*4+gamma]

    // W_hh row in registers as 16 packed f32x2
    ull w2[16];
    {
        const float* wr = w_hh + (size_t)tid * 32;
        #pragma unroll
        for (int q = 0; q < 16; q++) w2[q] = pk2(wr[2 * q], wr[2 * q + 1]);
    }
    float c = 0.0f, h = 0.0f;

    const float* preb = g_pre + (size_t)b * CC + tid;
    float preq[PF];
    #pragma unroll
    for (int i = 0; i < PF; i++) preq[i] = preb[(size_t)i * (NB * CC)];

    for (int t = 0; t < T; t += PF) {
        #pragma unroll
        for (int u = 0; u < PF; u++) {
            const int tt = t + u;
            const float p = preq[u];
            preq[u] = preb[(size_t)(tt + PF) * (NB * CC)];   // padded tail

            // rebuild packed h pairs via intra-warp shuffles (no smem, no bar)
            ull hh[16];
            #pragma unroll
            for (int q = 0; q < 16; q++) {
                float e0 = __shfl_sync(0xffffffffu, h, 2 * q);
                float e1 = __shfl_sync(0xffffffffu, h, 2 * q + 1);
                hh[q] = pk2(e0, e1);
            }

            ull a0 = mul2(hh[0], w2[0]);
            ull a1 = mul2(hh[1], w2[1]);
            #pragma unroll
            for (int q = 2; q < 16; q += 2) {
                a0 = fma2(hh[q],     w2[q],     a0);
                a1 = fma2(hh[q + 1], w2[q + 1], a1);
            }
            float lo, hi;
            upk2(add2(a0, a1), lo, hi);
            const float a = lo + hi + p;
            const float act = (gamma == 2) ? tanh_f(a) : sigm_f(a);

            const int par = tt & 1;
            sh_g[par][j * 4 + gamma] = act;
            __syncthreads();

            // c/h update (redundant in every warp; h stays in registers)
            float4 g4 = *(const float4*)&sh_g[par][j * 4];   // {i,f,g,o}
            c = fmaf(g4.y, c, g4.x * g4.z);
            h = g4.w * tanh_f(c);
            if (gamma == 0) g_hs[(size_t)tt * (NB * HH) + b * HH + j] = h;
        }
    }
}

// ---------------- K9: head  out[t] = lin2_b + sum_b lin2 . relu(lin1 h + b1)
__global__ __launch_bounds__(256) void k_head(const float* __restrict__ lin1,
                                              const float* __restrict__ b1,
                                              const float* __restrict__ lin2,
                                              const float* __restrict__ l2b,
                                              float* __restrict__ out) {
    __shared__ float s1[32][33];
    __shared__ float sb1[32], s2[32];
    const int tid = threadIdx.x;
    if (tid < 32) { sb1[tid] = b1[tid]; s2[tid] = lin2[tid]; }
    for (int i = tid; i < 1024; i += 256) s1[i >> 5][i & 31] = lin1[i];
    __syncthreads();

    const int warp = tid >> 5, lane = tid & 31;
    float l1r[32];
    #pragma unroll
    for (int k = 0; k < 32; k++) l1r[k] = s1[lane][k];
    const float l2l = s2[lane], b1l = sb1[lane];
    const float l2bias = l2b[0];

    const int t0 = (blockIdx.x * 8 + warp) * 8;
    for (int q = 0; q < 8; q++) {
        const int t = t0 + q;
        const float* hp = g_hs + (size_t)t * (NB * HH);
        float partial = 0.0f;
        #pragma unroll
        for (int bb = 0; bb < NB; bb++) {
            float hv = hp[bb * 32 + lane];
            float acc = b1l;
            #pragma unroll
            for (int k = 0; k < 32; k++)
                acc = fmaf(l1r[k], __shfl_sync(0xffffffffu, hv, k), acc);
            partial = fmaf(l2l, fmaxf(acc, 0.0f), partial);
        }
        #pragma unroll
        for (int o = 16; o; o >>= 1) partial += __shfl_xor_sync(0xffffffffu, partial, o);
        if (lane == 0) out[t] = partial + l2bias;
    }
}

// ---------------- launch ----------------
extern "C" void kernel_launch(void* const* d_in, const int* in_sizes, int n_in,
                              void* d_out, int out_size) {
    const float* state  = (const float*)d_in[0];
    const int*   ei     = (const int*)  d_in[1];
    const float* action = (const float*)d_in[2];
    const float* conv_w = (const float*)d_in[3];
    const float* conv_b = (const float*)d_in[4];
    const float* w_ih   = (const float*)d_in[5];
    const float* w_hh   = (const float*)d_in[6];
    const float* b_ih   = (const float*)d_in[7];
    const float* b_hh   = (const float*)d_in[8];
    const float* lin1_w = (const float*)d_in[9];
    const float* lin1_b = (const float*)d_in[10];
    const float* lin2_w = (const float*)d_in[11];
    const float* lin2_b = (const float*)d_in[12];
    float* out = (float*)d_out;

    k_init_deg<<<NN / 256, 256>>>();
    k_count   <<<NE / 256, 256>>>(ei);
    k_scan    <<<1, 1024>>>();
    k_fill    <<<NE / 256, 256>>>(ei);
    k_gemm_conv<<<NN / 128, 256>>>(state, conv_w);
    k_gather  <<<NN / 8, 256>>>(state, conv_b);
    k_gemm_pre<<<NN / 128, 256>>>(w_ih, action, b_ih, b_hh);
    k_lstm    <<<NB, 128>>>(w_hh);
    k_head    <<<T / 64, 256>>>(lin1_w, lin1_b, lin2_w, lin2_b, out);
}

// round 6
// speedup vs baseline: 1.5721x; 1.0198x over previous
#include <cuda_runtime.h>
#include <cstdint>

typedef unsigned long long ull;

static constexpr int NN = 49152;        // nodes
static constexpr int NE = 786432;       // edges
static constexpr int T  = 8192;         // LSTM sequence length (B)
static constexpr int NB = 6;            // ACT (LSTM batch)
static constexpr int CC = 128;          // channels
static constexpr int HH = 32;           // hidden
static constexpr int PF = 4;            // pre prefetch depth (steps)

// ---------------- scratch (static device globals; no allocs) ----------------
__device__ int   g_deg[NN];             // in-degree (no self loop)
__device__ float g_dinv[NN];
__device__ int   g_rowptr[NN + 1];
__device__ int   g_cursor[NN];
__device__ int   g_csrc[NE];
__device__ float g_xw[NN * CC];                    // state @ conv_w^T
__device__ float g_x [NN * CC];                    // relu(gcn)+state
__device__ float g_pre[(NN + PF * NB) * CC];       // LSTM input projection (+pad)
__device__ float g_hs[T * NB * HH];                // LSTM hidden states

// ---------------- f32x2 helpers (FFMA2 path, sm_100+) ----------------
__device__ __forceinline__ ull pk2(float lo, float hi) {
    ull r; asm("mov.b64 %0, {%1,%2};" : "=l"(r) : "f"(lo), "f"(hi)); return r;
}
__device__ __forceinline__ void upk2(ull v, float& lo, float& hi) {
    asm("mov.b64 {%0,%1}, %2;" : "=f"(lo), "=f"(hi) : "l"(v));
}
__device__ __forceinline__ ull fma2(ull a, ull b, ull c) {
    ull d; asm("fma.rn.f32x2 %0, %1, %2, %3;" : "=l"(d) : "l"(a), "l"(b), "l"(c)); return d;
}
__device__ __forceinline__ ull mul2(ull a, ull b) {
    ull d; asm("mul.rn.f32x2 %0, %1, %2;" : "=l"(d) : "l"(a), "l"(b)); return d;
}
__device__ __forceinline__ ull add2(ull a, ull b) {
    ull d; asm("add.rn.f32x2 %0, %1, %2;" : "=l"(d) : "l"(a), "l"(b)); return d;
}
__device__ __forceinline__ void lds2(unsigned addr, ull& a, ull& b) {
    asm volatile("ld.shared.v2.u64 {%0,%1}, [%2];" : "=l"(a), "=l"(b) : "r"(addr));
}

// R1's activation forms (measured-good)
__device__ __forceinline__ float sigm_f(float x) {
    float e = __expf(-x);
    return __fdividef(1.0f, 1.0f + e);
}
__device__ __forceinline__ float tanh_f(float x) {
    float e = __expf(2.0f * x);           // inf/0 handled: -> +/-1
    return 1.0f - __fdividef(2.0f, e + 1.0f);
}

// ---------------- K0: zero degree ----------------
__global__ void k_init_deg() {
    int i = blockIdx.x * blockDim.x + threadIdx.x;
    if (i < NN) g_deg[i] = 0;
}

// ---------------- K1: count in-degree at dst ----------------
__global__ void k_count(const int* __restrict__ ei) {
    int e = blockIdx.x * blockDim.x + threadIdx.x;
    if (e < NE) atomicAdd(&g_deg[ei[NE + e]], 1);
}

// ---------------- K2: fused scan (rowptr/cursor) + dinv, 1 block ------------
__global__ __launch_bounds__(1024) void k_scan() {
    __shared__ int warp_base[32];
    const int tid  = threadIdx.x;
    const int lane = tid & 31;
    const int wid  = tid >> 5;
    const int base = tid * 48;

    int s = 0;
    #pragma unroll 8
    for (int i = 0; i < 48; i++) s += g_deg[base + i];

    int incl = s;
    #pragma unroll
    for (int o = 1; o < 32; o <<= 1) {
        int n = __shfl_up_sync(0xffffffffu, incl, o);
        if (lane >= o) incl += n;
    }
    if (lane == 31) warp_base[wid] = incl;
    __syncthreads();
    if (wid == 0) {
        int t = warp_base[lane];
        int wi = t;
        #pragma unroll
        for (int o = 1; o < 32; o <<= 1) {
            int n = __shfl_up_sync(0xffffffffu, wi, o);
            if (lane >= o) wi += n;
        }
        warp_base[lane] = wi - t;
    }
    __syncthreads();

    int run = warp_base[wid] + (incl - s);
    #pragma unroll 8
    for (int i = 0; i < 48; i++) {
        int d = g_deg[base + i];
        g_rowptr[base + i] = run;
        g_cursor[base + i] = run;
        g_dinv  [base + i] = rsqrtf((float)(d + 1));
        run += d;
    }
    if (tid == 1023) g_rowptr[NN] = run;
}

// ---------------- K4: fill CSR (src lists by dst) ----------------
__global__ void k_fill(const int* __restrict__ ei) {
    int e = blockIdx.x * blockDim.x + threadIdx.x;
    if (e < NE) {
        int s = ei[e];
        int d = ei[NE + e];
        int pos = atomicAdd(&g_cursor[d], 1);
        g_csrc[pos] = s;
    }
}

// ---------------- K5: xw = state @ conv_w^T  (M=NN, N=128, K=128) ----------
__global__ __launch_bounds__(256, 2) void k_gemm_conv(const float* __restrict__ A,
                                                      const float* __restrict__ W) {
    __shared__ float As[16][132];
    __shared__ float Bs[16][132];
    const int tid  = threadIdx.x;
    const int bm   = blockIdx.x * 128;
    const int tRow = tid >> 4, tCol = tid & 15;
    float acc[8][8];
    #pragma unroll
    for (int i = 0; i < 8; i++)
        #pragma unroll
        for (int j = 0; j < 8; j++) acc[i][j] = 0.0f;

    for (int k0 = 0; k0 < 128; k0 += 16) {
        #pragma unroll
        for (int i = 0; i < 2; i++) {
            int aid = tid * 2 + i;            // 0..511
            int row = aid >> 2, c4 = aid & 3;
            float4 v = *(const float4*)(A + (size_t)(bm + row) * 128 + k0 + c4 * 4);
            As[c4 * 4 + 0][row] = v.x; As[c4 * 4 + 1][row] = v.y;
            As[c4 * 4 + 2][row] = v.z; As[c4 * 4 + 3][row] = v.w;
        }
        #pragma unroll
        for (int i = 0; i < 2; i++) {
            int wid = tid * 2 + i;
            int n = wid >> 2, c4 = wid & 3;
            float4 v = *(const float4*)(W + (size_t)n * 128 + k0 + c4 * 4);
            Bs[c4 * 4 + 0][n] = v.x; Bs[c4 * 4 + 1][n] = v.y;
            Bs[c4 * 4 + 2][n] = v.z; Bs[c4 * 4 + 3][n] = v.w;
        }
        __syncthreads();
        #pragma unroll
        for (int k = 0; k < 16; k++) {
            float4 a0 = *(const float4*)&As[k][tRow * 8];
            float4 a1 = *(const float4*)&As[k][tRow * 8 + 4];
            float4 b0 = *(const float4*)&Bs[k][tCol * 8];
            float4 b1 = *(const float4*)&Bs[k][tCol * 8 + 4];
            float av[8] = {a0.x, a0.y, a0.z, a0.w, a1.x, a1.y, a1.z, a1.w};
            float bv[8] = {b0.x, b0.y, b0.z, b0.w, b1.x, b1.y, b1.z, b1.w};
            #pragma unroll
            for (int i = 0; i < 8; i++)
                #pragma unroll
                for (int j = 0; j < 8; j++) acc[i][j] = fmaf(av[i], bv[j], acc[i][j]);
        }
        __syncthreads();
    }
    #pragma unroll
    for (int i = 0; i < 8; i++) {
        float4 o0 = {acc[i][0], acc[i][1], acc[i][2], acc[i][3]};
        float4 o1 = {acc[i][4], acc[i][5], acc[i][6], acc[i][7]};
        size_t base = (size_t)(bm + tRow * 8 + i) * 128 + tCol * 8;
        *(float4*)(g_xw + base)     = o0;
        *(float4*)(g_xw + base + 4) = o1;
    }
}

// ---------------- K6: gather-aggregate + bias + relu + residual -> g_x ------
__global__ __launch_bounds__(256) void k_gather(const float* __restrict__ state,
                                                const float* __restrict__ conv_b) {
    const int lane = threadIdx.x & 31;
    const int v = blockIdx.x * 8 + (threadIdx.x >> 5);
    const float dv = g_dinv[v];
    const float4* xwv = (const float4*)(g_xw + (size_t)v * CC);
    float4 a = xwv[lane];
    float4 acc;                      // self loop contribution (norm = dv*dv)
    acc.x = a.x * dv; acc.y = a.y * dv; acc.z = a.z * dv; acc.w = a.w * dv;

    const int s0 = g_rowptr[v], s1 = g_rowptr[v + 1];
    for (int base = s0; base < s1; base += 32) {
        int m = s1 - base; if (m > 32) m = 32;
        int   s_l = 0; float d_l = 0.0f;
        if (lane < m) { s_l = g_csrc[base + lane]; d_l = g_dinv[s_l]; }
        #pragma unroll 4
        for (int i = 0; i < m; i++) {
            int   s = __shfl_sync(0xffffffffu, s_l, i);
            float w = __shfl_sync(0xffffffffu, d_l, i);
            float4 xv = ((const float4*)(g_xw + (size_t)s * CC))[lane];
            acc.x = fmaf(xv.x, w, acc.x);
            acc.y = fmaf(xv.y, w, acc.y);
            acc.z = fmaf(xv.z, w, acc.z);
            acc.w = fmaf(xv.w, w, acc.w);
        }
    }
    float4 cb = ((const float4*)conv_b)[lane];
    float4 st = ((const float4*)(state + (size_t)v * CC))[lane];
    float4 r;
    r.x = fmaxf(acc.x * dv + cb.x, 0.0f) + st.x;
    r.y = fmaxf(acc.y * dv + cb.y, 0.0f) + st.y;
    r.z = fmaxf(acc.z * dv + cb.z, 0.0f) + st.z;
    r.w = fmaxf(acc.w * dv + cb.w, 0.0f) + st.w;
    ((float4*)(g_x + (size_t)v * CC))[lane] = r;
}

// ---------------- K7: pre = x @ w_ih[:, :128]^T + action*w_ih[:,128] + bias -
__global__ __launch_bounds__(256, 2) void k_gemm_pre(const float* __restrict__ Wih,
                                                     const float* __restrict__ action,
                                                     const float* __restrict__ bih,
                                                     const float* __restrict__ bhh) {
    __shared__ float As[16][132];
    __shared__ float Bs[16][132];
    const int tid  = threadIdx.x;
    const int bm   = blockIdx.x * 128;
    const int tRow = tid >> 4, tCol = tid & 15;
    const float* A = g_x;
    float acc[8][8];
    #pragma unroll
    for (int i = 0; i < 8; i++)
        #pragma unroll
        for (int j = 0; j < 8; j++) acc[i][j] = 0.0f;

    for (int k0 = 0; k0 < 128; k0 += 16) {
        #pragma unroll
        for (int i = 0; i < 2; i++) {
            int aid = tid * 2 + i;
            int row = aid >> 2, c4 = aid & 3;
            float4 v = *(const float4*)(A + (size_t)(bm + row) * 128 + k0 + c4 * 4);
            As[c4 * 4 + 0][row] = v.x; As[c4 * 4 + 1][row] = v.y;
            As[c4 * 4 + 2][row] = v.z; As[c4 * 4 + 3][row] = v.w;
        }
        // w_ih rows have stride 129 -> scalar loads
        #pragma unroll
        for (int i = 0; i < 8; i++) {
            int idx = tid + i * 256;          // 0..2047
            int n = idx >> 4, k = idx & 15;
            Bs[k][n] = Wih[(size_t)n * 129 + k0 + k];
        }
        __syncthreads();
        #pragma unroll
        for (int k = 0; k < 16; k++) {
            float4 a0 = *(const float4*)&As[k][tRow * 8];
            float4 a1 = *(const float4*)&As[k][tRow * 8 + 4];
            float4 b0 = *(const float4*)&Bs[k][tCol * 8];
            float4 b1 = *(const float4*)&Bs[k][tCol * 8 + 4];
            float av[8] = {a0.x, a0.y, a0.z, a0.w, a1.x, a1.y, a1.z, a1.w};
            float bv[8] = {b0.x, b0.y, b0.z, b0.w, b1.x, b1.y, b1.z, b1.w};
            #pragma unroll
            for (int i = 0; i < 8; i++)
                #pragma unroll
                for (int j = 0; j < 8; j++) acc[i][j] = fmaf(av[i], bv[j], acc[i][j]);
        }
        __syncthreads();
    }
    const int n0 = tCol * 8;
    float wc[8], bi[8];
    #pragma unroll
    for (int j = 0; j < 8; j++) {
        wc[j] = Wih[(size_t)(n0 + j) * 129 + 128];
        bi[j] = bih[n0 + j] + bhh[n0 + j];
    }
    #pragma unroll
    for (int i = 0; i < 8; i++) {
        int m = bm + tRow * 8 + i;
        float am = action[m];
        float o[8];
        #pragma unroll
        for (int j = 0; j < 8; j++) o[j] = acc[i][j] + am * wc[j] + bi[j];
        float4 o0 = {o[0], o[1], o[2], o[3]};
        float4 o1 = {o[4], o[5], o[6], o[7]};
        size_t base = (size_t)m * 128 + n0;
        *(float4*)(g_pre + base)     = o0;
        *(float4*)(g_pre + base + 4) = o1;
    }
}

// ---------------- K8: LSTM recurrence (R1 measured-best, verbatim) ----------
// block b handles batch lane b; warp gamma computes gate gamma (i,f,g,o rows)
__global__ __launch_bounds__(128, 1) void k_lstm(const float* __restrict__ w_hh) {
    const int b     = blockIdx.x;
    const int tid   = threadIdx.x;             // == row r of W_hh (0..127)
    const int gamma = tid >> 5;
    const int j     = tid & 31;
    __shared__ __align__(16) float sh_h[4][32];     // per-warp private h copy
    __shared__ __align__(16) float sh_g[2][128];    // [parity][j*4+gamma]

    // W_hh row in registers as 16 packed f32x2
    ull w2[16];
    {
        const float* wr = w_hh + (size_t)tid * 32;
        #pragma unroll
        for (int q = 0; q < 16; q++) w2[q] = pk2(wr[2 * q], wr[2 * q + 1]);
    }
    float c = 0.0f;
    sh_h[gamma][j] = 0.0f;

    const float* preb = g_pre + (size_t)b * CC + tid;
    float preq[PF];
    #pragma unroll
    for (int i = 0; i < PF; i++) preq[i] = preb[(size_t)i * (NB * CC)];

    const unsigned hb = (unsigned)__cvta_generic_to_shared(&sh_h[gamma][0]);
    __syncthreads();

    for (int t = 0; t < T; t += PF) {
        #pragma unroll
        for (int u = 0; u < PF; u++) {
            const int tt = t + u;
            const float p = preq[u];

            ull hh[16];
            #pragma unroll
            for (int q = 0; q < 8; q++) lds2(hb + 16 * q, hh[2 * q], hh[2 * q + 1]);

            preq[u] = preb[(size_t)(tt + PF) * (NB * CC)];   // padded tail

            ull a0 = mul2(hh[0], w2[0]);
            ull a1 = mul2(hh[1], w2[1]);
            #pragma unroll
            for (int q = 2; q < 16; q += 2) {
                a0 = fma2(hh[q],     w2[q],     a0);
                a1 = fma2(hh[q + 1], w2[q + 1], a1);
            }
            float lo, hi;
            upk2(add2(a0, a1), lo, hi);
            const float a = lo + hi + p;
            const float act = (gamma == 2) ? tanh_f(a) : sigm_f(a);

            const int par = tt & 1;
            sh_g[par][j * 4 + gamma] = act;
            __syncthreads();

            float4 g4 = *(const float4*)&sh_g[par][j * 4];   // {i,f,g,o}
            c = fmaf(g4.y, c, g4.x * g4.z);
            const float hnew = g4.w * tanh_f(c);
            sh_h[gamma][j] = hnew;
            if (gamma == 0) g_hs[(size_t)tt * (NB * HH) + b * HH + j] = hnew;
            __syncwarp();
        }
    }
}

// ---------------- K9: head  out[t] = lin2_b + sum_b lin2 . relu(lin1 h + b1)
__global__ __launch_bounds__(256) void k_head(const float* __restrict__ lin1,
                                              const float* __restrict__ b1,
                                              const float* __restrict__ lin2,
                                              const float* __restrict__ l2b,
                                              float* __restrict__ out) {
    __shared__ float s1[32][33];
    __shared__ float sb1[32], s2[32];
    const int tid = threadIdx.x;
    if (tid < 32) { sb1[tid] = b1[tid]; s2[tid] = lin2[tid]; }
    for (int i = tid; i < 1024; i += 256) s1[i >> 5][i & 31] = lin1[i];
    __syncthreads();

    const int warp = tid >> 5, lane = tid & 31;
    float l1r[32];
    #pragma unroll
    for (int k = 0; k < 32; k++) l1r[k] = s1[lane][k];
    const float l2l = s2[lane], b1l = sb1[lane];
    const float l2bias = l2b[0];

    const int t0 = (blockIdx.x * 8 + warp) * 8;
    for (int q = 0; q < 8; q++) {
        const int t = t0 + q;
        const float* hp = g_hs + (size_t)t * (NB * HH);
        float partial = 0.0f;
        #pragma unroll
        for (int bb = 0; bb < NB; bb++) {
            float hv = hp[bb * 32 + lane];
            float acc = b1l;
            #pragma unroll
            for (int k = 0; k < 32; k++)
                acc = fmaf(l1r[k], __shfl_sync(0xffffffffu, hv, k), acc);
            partial = fmaf(l2l, fmaxf(acc, 0.0f), partial);
        }
        #pragma unroll
        for (int o = 16; o; o >>= 1) partial += __shfl_xor_sync(0xffffffffu, partial, o);
        if (lane == 0) out[t] = partial + l2bias;
    }
}

// ---------------- launch ----------------
extern "C" void kernel_launch(void* const* d_in, const int* in_sizes, int n_in,
                              void* d_out, int out_size) {
    const float* state  = (const float*)d_in[0];
    const int*   ei     = (const int*)  d_in[1];
    const float* action = (const float*)d_in[2];
    const float* conv_w = (const float*)d_in[3];
    const float* conv_b = (const float*)d_in[4];
    const float* w_ih   = (const float*)d_in[5];
    const float* w_hh   = (const float*)d_in[6];
    const float* b_ih   = (const float*)d_in[7];
    const float* b_hh   = (const float*)d_in[8];
    const float* lin1_w = (const float*)d_in[9];
    const float* lin1_b = (const float*)d_in[10];
    const float* lin2_w = (const float*)d_in[11];
    const float* lin2_b = (const float*)d_in[12];
    float* out = (float*)d_out;

    k_init_deg<<<NN / 256, 256>>>();
    k_count   <<<NE / 256, 256>>>(ei);
    k_scan    <<<1, 1024>>>();
    k_fill    <<<NE / 256, 256>>>(ei);
    k_gemm_conv<<<NN / 128, 256>>>(state, conv_w);
    k_gather  <<<NN / 8, 256>>>(state, conv_b);
    k_gemm_pre<<<NN / 128, 256>>>(w_ih, action, b_ih, b_hh);
    k_lstm    <<<NB, 128>>>(w_hh);
    k_head    <<<T / 64, 256>>>(lin1_w, lin1_b, lin2_w, lin2_b, out);
}